// round 15
// baseline (speedup 1.0000x reference)
#include <cuda_runtime.h>
#include <cstdint>

// Problem constants
#define HN    16
#define AD    64
#define SQ    1024
#define NB    4
#define DM    1024
#define KREL  16
#define SN_EPS 1e-8f

// ---------------------------------------------------------------------------
// Scratch (device globals: no runtime allocation allowed).
// Packed bf16x2 convention: u32 = [bf16(x_even) low | bf16(x_odd) high],
// pairs along the K-contiguous dimension.
// ---------------------------------------------------------------------------
__device__ __align__(16) float    g_q   [NB * HN * SQ * AD];      // fp32 (rq needs it)
__device__ __align__(16) uint32_t g_k_h [NB * HN * SQ * AD / 2];  // [B,H,S,32] pairs along d
__device__ __align__(16) uint32_t g_k_l [NB * HN * SQ * AD / 2];
__device__ __align__(16) unsigned short g_vT_h[NB * HN * AD * SQ]; // [B,H,AD,S] transposed
__device__ __align__(16) unsigned short g_vT_l[NB * HN * AD * SQ];
__device__ __align__(16) uint32_t g_ctx_h[NB * SQ * DM / 2];      // [B,S,512]
__device__ __align__(16) uint32_t g_ctx_l[NB * SQ * DM / 2];
__device__ __align__(16) uint32_t g_iQ_h[4096 * 512];
__device__ __align__(16) uint32_t g_iQ_l[4096 * 512];
__device__ __align__(16) uint32_t g_Wa_h[3072 * 512];
__device__ __align__(16) uint32_t g_Wa_l[3072 * 512];
__device__ __align__(16) uint32_t g_Wo_h[1024 * 512];
__device__ __align__(16) uint32_t g_Wo_l[1024 * 512];

// ===========================================================================
// Helpers (baseline sm_80+ PTX only)
// ===========================================================================
__device__ __forceinline__ void cp16(uint32_t saddr, const void* g) {
    asm volatile("cp.async.cg.shared.global [%0], [%1], 16;\n" :: "r"(saddr), "l"(g));
}
#define CP_COMMIT() asm volatile("cp.async.commit_group;\n" ::: "memory")
#define CP_WAIT(n)  asm volatile("cp.async.wait_group %0;\n" :: "n"(n) : "memory")

__device__ __forceinline__ uint32_t smem_u32(const void* p) {
    uint32_t a;
    asm("{ .reg .u64 t; cvta.to.shared.u64 t, %1; cvt.u32.u64 %0, t; }"
        : "=r"(a) : "l"(p));
    return a;
}

__device__ __forceinline__ void mma_bf16(float c[4], const uint32_t a[4], const uint32_t b[2]) {
    asm volatile(
        "mma.sync.aligned.m16n8k16.row.col.f32.bf16.bf16.f32 "
        "{%0,%1,%2,%3}, {%4,%5,%6,%7}, {%8,%9}, {%0,%1,%2,%3};"
        : "+f"(c[0]), "+f"(c[1]), "+f"(c[2]), "+f"(c[3])
        : "r"(a[0]), "r"(a[1]), "r"(a[2]), "r"(a[3]), "r"(b[0]), "r"(b[1]));
}

// hi_i = bf16-truncate(x_i) (exact), lo_i = x_i - hi_i (|lo|<=2^-8|x|, bf16
// re-truncation residual <= 2^-16 |x|). Packed [x0 | x1].
__device__ __forceinline__ void bsplit(float x0, float x1, uint32_t& hi, uint32_t& lo) {
    uint32_t h0 = __float_as_uint(x0) & 0xFFFF0000u;
    uint32_t h1 = __float_as_uint(x1) & 0xFFFF0000u;
    hi = __byte_perm(h0, h1, 0x7632);
    float l0 = x0 - __uint_as_float(h0);
    float l1 = x1 - __uint_as_float(h1);
    lo = __byte_perm(__float_as_uint(l0), __float_as_uint(l1), 0x7632);
}

// ===========================================================================
// fp32 -> packed bf16x2 hi/lo converter (bandwidth-bound, grid-stride)
// ===========================================================================
__global__ void cvt_kernel(const float* __restrict__ src, uint32_t* __restrict__ h,
                           uint32_t* __restrict__ l, int npairs)
{
    for (int i = blockIdx.x * blockDim.x + threadIdx.x; i < npairs;
         i += gridDim.x * blockDim.x) {
        float2 v = ((const float2*)src)[i];
        uint32_t hi, lo;
        bsplit(v.x, v.y, hi, lo);
        h[i] = hi;
        l[i] = lo;
    }
}

// ===========================================================================
// 3xBF16 GEMM on PRE-SPLIT operands. Pass-major mma order: same-accumulator
// RAW reuse distance 4 (was 1) -> tensor-pipe ILP.
// ===========================================================================
#define GKU    512
#define ROWU   20
#define TILEU  (128 * ROWU)
#define GSM_BYTES (2 * 4 * TILEU * 4)      // 2 buf x 4 tiles (Ah,Al,Wh,Wl)

template <int MODE>
__global__ __launch_bounds__(256, 2)
void tc_gemm(const uint32_t* __restrict__ Ahg, const uint32_t* __restrict__ Alg,
             const uint32_t* __restrict__ Whg, const uint32_t* __restrict__ Wlg,
             const float* __restrict__ bias, float* __restrict__ C, int N)
{
    extern __shared__ __align__(16) uint32_t smu[];

    const int tid  = threadIdx.x;
    const int wid  = tid >> 5;
    const int lane = tid & 31;
    const int g    = lane >> 2;
    const int tig  = lane & 3;
    const int wm   = wid >> 2;
    const int wn   = wid & 3;
    const int mbase = wm * 64;
    const int nbase = wn * 32;

    const int bx = blockIdx.x;
    const int by = blockIdx.y;

    const uint32_t* srcs[4] = {
        Ahg + (long)(by * 128) * GKU, Alg + (long)(by * 128) * GKU,
        Whg + (long)(bx * 128) * GKU, Wlg + (long)(bx * 128) * GKU };

    const uint32_t sbase = smem_u32(smu);
    auto load_chunk = [&](int kc, int buf) {
#pragma unroll
        for (int t = 0; t < 4; t++) {
#pragma unroll
            for (int i = 0; i < 2; i++) {
                int idx = tid + i * 256;          // 0..511
                int r = idx >> 2;                 // row 0..127
                int q = idx & 3;                  // u32 quad
                cp16(sbase + (uint32_t)(((buf * 4 + t) * TILEU + r * ROWU + q * 4) * 4),
                     srcs[t] + (long)r * GKU + kc * 16 + q * 4);
            }
        }
    };

    float acc[4][4][4];
#pragma unroll
    for (int mi = 0; mi < 4; mi++)
#pragma unroll
        for (int ni = 0; ni < 4; ni++)
#pragma unroll
            for (int r = 0; r < 4; r++) acc[mi][ni][r] = 0.f;

    load_chunk(0, 0); CP_COMMIT();
    load_chunk(1, 1); CP_COMMIT();

    const int NCH = 32;                    // 1024 / 32
    for (int k0 = 0; k0 < NCH; k0++) {
        const int buf = k0 & 1;
        if (k0 + 1 < NCH) { CP_WAIT(1); } else { CP_WAIT(0); }
        __syncthreads();

        const uint32_t* Ah = smu + (buf * 4 + 0) * TILEU;
        const uint32_t* Al = smu + (buf * 4 + 1) * TILEU;
        const uint32_t* Wh = smu + (buf * 4 + 2) * TILEU;
        const uint32_t* Wl = smu + (buf * 4 + 3) * TILEU;
#pragma unroll
        for (int kk = 0; kk < 2; kk++) {
            const int kc = kk * 8;
            uint32_t bh[4][2], bl[4][2];
#pragma unroll
            for (int ni = 0; ni < 4; ni++) {
                const int r0 = (nbase + ni * 8 + g) * ROWU + kc + tig;
                bh[ni][0] = Wh[r0];     bh[ni][1] = Wh[r0 + 4];
                bl[ni][0] = Wl[r0];     bl[ni][1] = Wl[r0 + 4];
            }
#pragma unroll
            for (int mi = 0; mi < 4; mi++) {
                const int r0 = (mbase + mi * 16 + g) * ROWU + kc + tig;
                const int r8 = r0 + 8 * ROWU;
                uint32_t ah[4], al[4];
                ah[0] = Ah[r0]; ah[1] = Ah[r8]; ah[2] = Ah[r0 + 4]; ah[3] = Ah[r8 + 4];
                al[0] = Al[r0]; al[1] = Al[r8]; al[2] = Al[r0 + 4]; al[3] = Al[r8 + 4];
                // pass-major: reuse distance 4 on each accumulator
#pragma unroll
                for (int ni = 0; ni < 4; ni++) mma_bf16(acc[mi][ni], ah, bh[ni]);
#pragma unroll
                for (int ni = 0; ni < 4; ni++) mma_bf16(acc[mi][ni], ah, bl[ni]);
#pragma unroll
                for (int ni = 0; ni < 4; ni++) mma_bf16(acc[mi][ni], al, bh[ni]);
            }
        }
        __syncthreads();
        if (k0 + 2 < NCH) { load_chunk(k0 + 2, buf); CP_COMMIT(); }
    }

    // Epilogue: c-frag (m16n8) rows g,g+8; cols 2tig,2tig+1 (adjacent pair)
#pragma unroll
    for (int ni = 0; ni < 4; ni++) {
        const int gcol = bx * 128 + nbase + ni * 8 + 2 * tig;
        const float b0 = bias[gcol];
        const float b1 = bias[gcol + 1];
        const int which = gcol >> 10;
        const int hh = (gcol >> 6) & 15;
        const int dd = gcol & 63;
#pragma unroll
        for (int mi = 0; mi < 4; mi++) {
#pragma unroll
            for (int h = 0; h < 2; h++) {
                const int rr = by * 128 + mbase + mi * 16 + g + h * 8;
                float2 o;
                o.x = acc[mi][ni][2 * h + 0] + b0;
                o.y = acc[mi][ni][2 * h + 1] + b1;
                if (MODE == 0) {
                    const int bb = rr >> 10, ss = rr & 1023;
                    const long bhq = (long)(bb * HN + hh);
                    if (which == 0) {
                        *(float2*)(g_q + (bhq * SQ + ss) * AD + dd) = o;
                    } else if (which == 1) {
                        uint32_t hi, lo;
                        bsplit(o.x, o.y, hi, lo);
                        const long idx = (bhq * SQ + ss) * 32 + (dd >> 1);
                        g_k_h[idx] = hi;
                        g_k_l[idx] = lo;
                    } else {
                        uint32_t hi, lo;
                        bsplit(o.x, o.y, hi, lo);
                        const long base = (bhq * AD + dd) * SQ + ss;
                        g_vT_h[base]      = (unsigned short)(hi & 0xFFFFu);
                        g_vT_h[base + SQ] = (unsigned short)(hi >> 16);
                        g_vT_l[base]      = (unsigned short)(lo & 0xFFFFu);
                        g_vT_l[base + SQ] = (unsigned short)(lo >> 16);
                    }
                } else {
                    *(float2*)(C + (long)rr * N + gcol) = o;
                }
            }
        }
    }
}

// ===========================================================================
// Tensor-core attention, register P-reuse + pass-major mma order.
// Grid (8,16,4), 256 thr, q tile 128 rows (warp w owns [16w,16w+16)).
// kv tiles 32 rows, double-buffered. smem ~103 KB -> 2 CTAs/SM.
// ===========================================================================
#define O_QH   0                              // [128][36]
#define O_QL   (O_QH + 128*36)                // 4608
#define O_KV   (O_QL + 128*36)                // 2 buf x 4864
#define KVBUF  4864                           // KH[32][36] KL[32][36] VH[64][20] VL[64][20]
#define KV_KH  0
#define KV_KL  1152
#define KV_VH  2304
#define KV_VL  3584
#define O_RELS (O_KV + 2*KVBUF)               // fp32 [33][68]
#define O_RQS  (O_RELS + 33*68)               // fp32 [128][36]
#define A_TOTU (O_RQS + 128*36)
#define A_BYTES (A_TOTU * 4)                  // 103,184 B -> 2 CTAs/SM

__global__ __launch_bounds__(256, 2)
void attn_mma(const float* __restrict__ rel_emb, const float* __restrict__ snb_p)
{
    extern __shared__ __align__(16) uint32_t smu[];
    float* smf = (float*)smu;

    const int tid  = threadIdx.x;
    const int wid  = tid >> 5;
    const int lane = tid & 31;
    const int g    = lane >> 2;
    const int tig  = lane & 3;
    const int qt = blockIdx.x, h = blockIdx.y, b = blockIdx.z;
    const int bh = b * HN + h;
    const int q0 = qt * 128;
    const int mb = wid * 16;
    const float snb = __ldg(snb_p);

    const uint32_t sb = smem_u32(smu);

    // ---- preamble: stage q fp32 (transiently in KV area, stride 68) + rels
    const float* Qg = g_q + ((long)bh * SQ + q0) * AD;
#pragma unroll
    for (int i = 0; i < 8; i++) {
        int idx = tid + i * 256;
        int r = idx >> 4, c = idx & 15;
        cp16(sb + (uint32_t)((O_KV + r * 68 + c * 4) * 4), Qg + r * AD + c * 4);
    }
    for (int i = tid; i < 33 * 16; i += 256) {
        int r = i >> 4, c = i & 15;
        cp16(sb + (uint32_t)((O_RELS + r * 68 + c * 4) * 4), rel_emb + r * 64 + c * 4);
    }
    CP_COMMIT();
    CP_WAIT(0);
    __syncthreads();

    // q -> bf16 hi/lo (once per block)
    float* q32 = smf + O_KV;                 // [128][68] fp32 (transient)
    for (int i = tid; i < 128 * 32; i += 256) {
        int r = i >> 5, c = i & 31;
        float2 v = *(const float2*)&q32[r * 68 + c * 2];
        uint32_t hi, lo;
        bsplit(v.x, v.y, hi, lo);
        smu[O_QH + r * 36 + c] = hi;
        smu[O_QL + r * 36 + c] = lo;
    }
    // rq[r][p] = q_r . rel_emb[p]  (fp32)
    float* relf = smf + O_RELS;
    float* rqs  = smf + O_RQS;
    for (int i = tid; i < 128 * 33; i += 256) {
        int r = i / 33, p = i - r * 33;
        float s = 0.f;
#pragma unroll 16
        for (int d = 0; d < 64; d++) s = fmaf(q32[r * 68 + d], relf[p * 68 + d], s);
        rqs[r * 36 + p] = s;
    }
    __syncthreads();            // q32 reads done; KV area now free

    auto load_kv = [&](int kt, int buf) {
        const uint32_t kvb = sb + (uint32_t)((O_KV + buf * KVBUF) * 4);
        const uint32_t* Khg = g_k_h + ((long)bh * SQ + kt * 32) * 32;
        const uint32_t* Klg = g_k_l + ((long)bh * SQ + kt * 32) * 32;
        const unsigned short* Vhg = g_vT_h + (long)bh * AD * SQ + kt * 32;
        const unsigned short* Vlg = g_vT_l + (long)bh * AD * SQ + kt * 32;
        {   // K tiles: 32 rows x 8 quads, 256 threads -> 1 each per tile
            int r = tid >> 3, c = tid & 7;
            uint32_t so = (uint32_t)((r * 36 + c * 4) * 4);
            cp16(kvb + KV_KH * 4 + so, Khg + r * 32 + c * 4);
            cp16(kvb + KV_KL * 4 + so, Klg + r * 32 + c * 4);
        }
        {   // V tiles: 64 d-rows x 4 quads (16 u32 = 32 shorts along s)
            int d = tid >> 2, c = tid & 3;
            uint32_t so = (uint32_t)((d * 20 + c * 4) * 4);
            cp16(kvb + KV_VH * 4 + so, Vhg + (long)d * SQ + c * 8);
            cp16(kvb + KV_VL * 4 + so, Vlg + (long)d * SQ + c * 8);
        }
    };
    load_kv(0, 0); CP_COMMIT();
    load_kv(1, 1); CP_COMMIT();

    float oacc[8][4];
#pragma unroll
    for (int ni = 0; ni < 8; ni++)
#pragma unroll
        for (int r = 0; r < 4; r++) oacc[ni][r] = 0.f;
    float denp0 = 0.f, denp1 = 0.f;

    const uint32_t* QH = smu + O_QH;
    const uint32_t* QL = smu + O_QL;
    const int ig0 = q0 + mb + g;

    for (int kt = 0; kt < 32; kt++) {
        const int buf = kt & 1;
        if (kt + 1 < 32) { CP_WAIT(1); } else { CP_WAIT(0); }
        __syncthreads();
        const uint32_t* KH = smu + O_KV + buf * KVBUF + KV_KH;
        const uint32_t* KL = smu + O_KV + buf * KVBUF + KV_KL;
        const uint32_t* VH = smu + O_KV + buf * KVBUF + KV_VH;
        const uint32_t* VL = smu + O_KV + buf * KVBUF + KV_VL;

        // --- S = q k^T over 32 key rows; sacc[ni] covers cols ni*8..+7
        float sacc[4][4];
#pragma unroll
        for (int ni = 0; ni < 4; ni++)
#pragma unroll
            for (int r = 0; r < 4; r++) sacc[ni][r] = 0.f;
#pragma unroll
        for (int kk = 0; kk < 4; kk++) {
            const int kc = kk * 8;
            const int r0 = (mb + g) * 36 + kc + tig;
            const int r8 = r0 + 8 * 36;
            uint32_t ah[4], al[4];
            ah[0] = QH[r0]; ah[1] = QH[r8]; ah[2] = QH[r0 + 4]; ah[3] = QH[r8 + 4];
            al[0] = QL[r0]; al[1] = QL[r8]; al[2] = QL[r0 + 4]; al[3] = QL[r8 + 4];
            uint32_t kbh[4][2], kbl[4][2];
#pragma unroll
            for (int ni = 0; ni < 4; ni++) {
                const int b0 = (ni * 8 + g) * 36 + kc + tig;
                kbh[ni][0] = KH[b0]; kbh[ni][1] = KH[b0 + 4];
                kbl[ni][0] = KL[b0]; kbl[ni][1] = KL[b0 + 4];
            }
            // pass-major: reuse distance 4
#pragma unroll
            for (int ni = 0; ni < 4; ni++) mma_bf16(sacc[ni], ah, kbh[ni]);
#pragma unroll
            for (int ni = 0; ni < 4; ni++) mma_bf16(sacc[ni], ah, kbl[ni]);
#pragma unroll
            for (int ni = 0; ni < 4; ni++) mma_bf16(sacc[ni], al, kbh[ni]);
        }

        // --- elementwise in registers: t = relu((S+rel)/8 + b)^2, split ---
        uint32_t tha[4], tla[4], thb[4], tlb[4];
#pragma unroll
        for (int ni = 0; ni < 4; ni++) {
            const int cbase = ni * 8 + 2 * tig;
            const int jbase = kt * 32 + cbase;
            {   // row g
                int d0 = jbase - ig0;     d0 = (d0 < -KREL) ? -KREL : ((d0 > KREL) ? KREL : d0);
                int d1 = jbase + 1 - ig0; d1 = (d1 < -KREL) ? -KREL : ((d1 > KREL) ? KREL : d1);
                float s0 = (sacc[ni][0] + rqs[(mb + g) * 36 + d0 + KREL]) * 0.125f + snb;
                float s1 = (sacc[ni][1] + rqs[(mb + g) * 36 + d1 + KREL]) * 0.125f + snb;
                s0 = fmaxf(s0, 0.f); s1 = fmaxf(s1, 0.f);
                float t0 = s0 * s0, t1 = s1 * s1;
                denp0 += t0 + t1;
                bsplit(t0, t1, tha[ni], tla[ni]);
            }
            {   // row g+8
                int d0 = jbase - (ig0 + 8);     d0 = (d0 < -KREL) ? -KREL : ((d0 > KREL) ? KREL : d0);
                int d1 = jbase + 1 - (ig0 + 8); d1 = (d1 < -KREL) ? -KREL : ((d1 > KREL) ? KREL : d1);
                float s0 = (sacc[ni][2] + rqs[(mb + g + 8) * 36 + d0 + KREL]) * 0.125f + snb;
                float s1 = (sacc[ni][3] + rqs[(mb + g + 8) * 36 + d1 + KREL]) * 0.125f + snb;
                s0 = fmaxf(s0, 0.f); s1 = fmaxf(s1, 0.f);
                float t0 = s0 * s0, t1 = s1 * s1;
                denp1 += t0 + t1;
                bsplit(t0, t1, thb[ni], tlb[ni]);
            }
        }

        // --- O += t V ; A-frag is the in-register t; pass-major (distance 8)
#pragma unroll
        for (int kk2 = 0; kk2 < 2; kk2++) {
            uint32_t ah[4], al[4];
            ah[0] = tha[2 * kk2];     al[0] = tla[2 * kk2];
            ah[1] = thb[2 * kk2];     al[1] = tlb[2 * kk2];
            ah[2] = tha[2 * kk2 + 1]; al[2] = tla[2 * kk2 + 1];
            ah[3] = thb[2 * kk2 + 1]; al[3] = tlb[2 * kk2 + 1];
#pragma unroll
            for (int ni = 0; ni < 8; ni++) {     // pass hh
                const int b0 = (ni * 8 + g) * 20 + kk2 * 8 + tig;
                uint32_t bh2[2] = { VH[b0], VH[b0 + 4] };
                mma_bf16(oacc[ni], ah, bh2);
            }
#pragma unroll
            for (int ni = 0; ni < 8; ni++) {     // pass hl
                const int b0 = (ni * 8 + g) * 20 + kk2 * 8 + tig;
                uint32_t bl2[2] = { VL[b0], VL[b0 + 4] };
                mma_bf16(oacc[ni], ah, bl2);
            }
#pragma unroll
            for (int ni = 0; ni < 8; ni++) {     // pass lh
                const int b0 = (ni * 8 + g) * 20 + kk2 * 8 + tig;
                uint32_t bh2[2] = { VH[b0], VH[b0 + 4] };
                mma_bf16(oacc[ni], al, bh2);
            }
        }
        __syncthreads();        // all warps done with kv[buf] before refill
        if (kt + 2 < 32) { load_kv(kt + 2, buf); CP_COMMIT(); }
    }

    // deterministic den reduction across the 4 tig lanes
    denp0 += __shfl_xor_sync(0xffffffffu, denp0, 1);
    denp0 += __shfl_xor_sync(0xffffffffu, denp0, 2);
    denp1 += __shfl_xor_sync(0xffffffffu, denp1, 1);
    denp1 += __shfl_xor_sync(0xffffffffu, denp1, 2);
    const float inv0 = 1.f / (denp0 + SN_EPS);
    const float inv1 = 1.f / (denp1 + SN_EPS);

    // ctx written pre-split for tc_gemm<1>
    const long row0 = (long)(b * SQ + q0 + mb + g);
#pragma unroll
    for (int ni = 0; ni < 8; ni++) {
        const int c = h * 32 + ni * 4 + tig;     // u32 col in [512]
        uint32_t hi, lo;
        bsplit(oacc[ni][0] * inv0, oacc[ni][1] * inv0, hi, lo);
        g_ctx_h[row0 * 512 + c] = hi;
        g_ctx_l[row0 * 512 + c] = lo;
        bsplit(oacc[ni][2] * inv1, oacc[ni][3] * inv1, hi, lo);
        g_ctx_h[(row0 + 8) * 512 + c] = hi;
        g_ctx_l[(row0 + 8) * 512 + c] = lo;
    }
}

// ===========================================================================
extern "C" void kernel_launch(void* const* d_in, const int* in_sizes, int n_in,
                              void* d_out, int out_size)
{
    (void)in_sizes; (void)n_in; (void)out_size;
    const float* iQ  = (const float*)d_in[0];
    const float* Wa  = (const float*)d_in[1];
    const float* ba  = (const float*)d_in[2];
    const float* rel = (const float*)d_in[3];
    const float* snb = (const float*)d_in[4];
    const float* Wo  = (const float*)d_in[5];
    const float* bo  = (const float*)d_in[6];
    float* out = (float*)d_out;

    cudaFuncSetAttribute(tc_gemm<0>, cudaFuncAttributeMaxDynamicSharedMemorySize, GSM_BYTES);
    cudaFuncSetAttribute(tc_gemm<1>, cudaFuncAttributeMaxDynamicSharedMemorySize, GSM_BYTES);
    cudaFuncSetAttribute(attn_mma,   cudaFuncAttributeMaxDynamicSharedMemorySize, A_BYTES);

    uint32_t *iQh, *iQl, *Wah, *Wal, *Woh, *Wol;
    cudaGetSymbolAddress((void**)&iQh, g_iQ_h); cudaGetSymbolAddress((void**)&iQl, g_iQ_l);
    cudaGetSymbolAddress((void**)&Wah, g_Wa_h); cudaGetSymbolAddress((void**)&Wal, g_Wa_l);
    cudaGetSymbolAddress((void**)&Woh, g_Wo_h); cudaGetSymbolAddress((void**)&Wol, g_Wo_l);

    // 0) pre-split inputs to packed bf16 hi/lo
    cvt_kernel<<<2048, 256>>>(iQ, iQh, iQl, 4096 * 512);
    cvt_kernel<<<2048, 256>>>(Wa, Wah, Wal, 3072 * 512);
    cvt_kernel<<<1024, 256>>>(Wo, Woh, Wol, 1024 * 512);

    // 1) QKV projection -> g_q (fp32), g_k hi/lo, g_vT hi/lo
    tc_gemm<0><<<dim3(3072 / 128, 4096 / 128), 256, GSM_BYTES>>>(iQh, iQl, Wah, Wal, ba, nullptr, 3072);

    // 2) tensor-core attention + SparseNormer -> g_ctx hi/lo
    attn_mma<<<dim3(SQ / 128, HN, NB), 256, A_BYTES>>>(rel, snb);

    // 3) output projection -> out
    {
        uint32_t *ch, *cl;
        cudaGetSymbolAddress((void**)&ch, g_ctx_h);
        cudaGetSymbolAddress((void**)&cl, g_ctx_l);
        tc_gemm<1><<<dim3(1024 / 128, 4096 / 128), 256, GSM_BYTES>>>(ch, cl, Woh, Wol, bo, out, 1024);
    }
}

// round 17
// speedup vs baseline: 1.0247x; 1.0247x over previous
#include <cuda_runtime.h>
#include <cstdint>

// Problem constants
#define HN    16
#define AD    64
#define SQ    1024
#define NB    4
#define DM    1024
#define KREL  16
#define SN_EPS 1e-8f

// ---------------------------------------------------------------------------
// Scratch (device globals: no runtime allocation allowed).
// Packed bf16x2 convention: u32 = [bf16(x_even) low | bf16(x_odd) high],
// pairs along the K-contiguous dimension.
// ---------------------------------------------------------------------------
__device__ __align__(16) float    g_q   [NB * HN * SQ * AD];      // fp32 (rq needs it)
__device__ __align__(16) uint32_t g_k_h [NB * HN * SQ * AD / 2];  // [B,H,S,32] pairs along d
__device__ __align__(16) uint32_t g_k_l [NB * HN * SQ * AD / 2];
__device__ __align__(16) unsigned short g_vT_h[NB * HN * AD * SQ]; // [B,H,AD,S] transposed
__device__ __align__(16) unsigned short g_vT_l[NB * HN * AD * SQ];
__device__ __align__(16) float    g_ctx [NB * SQ * DM];           // fp32 [B,S,1024]

// ===========================================================================
// Helpers (baseline sm_80+ PTX only)
// ===========================================================================
__device__ __forceinline__ void cp16(uint32_t saddr, const void* g) {
    asm volatile("cp.async.cg.shared.global [%0], [%1], 16;\n" :: "r"(saddr), "l"(g));
}
#define CP_COMMIT() asm volatile("cp.async.commit_group;\n" ::: "memory")
#define CP_WAIT(n)  asm volatile("cp.async.wait_group %0;\n" :: "n"(n) : "memory")

__device__ __forceinline__ uint32_t smem_u32(const void* p) {
    uint32_t a;
    asm("{ .reg .u64 t; cvta.to.shared.u64 t, %1; cvt.u32.u64 %0, t; }"
        : "=r"(a) : "l"(p));
    return a;
}

__device__ __forceinline__ void mma_bf16(float c[4], const uint32_t a[4], const uint32_t b[2]) {
    asm volatile(
        "mma.sync.aligned.m16n8k16.row.col.f32.bf16.bf16.f32 "
        "{%0,%1,%2,%3}, {%4,%5,%6,%7}, {%8,%9}, {%0,%1,%2,%3};"
        : "+f"(c[0]), "+f"(c[1]), "+f"(c[2]), "+f"(c[3])
        : "r"(a[0]), "r"(a[1]), "r"(a[2]), "r"(a[3]), "r"(b[0]), "r"(b[1]));
}

// hi_i = bf16-truncate(x_i) (exact), lo_i = x_i - hi_i (|lo|<=2^-8|x|, bf16
// re-truncation residual <= 2^-16 |x|). Packed [x0 | x1].
__device__ __forceinline__ void bsplit(float x0, float x1, uint32_t& hi, uint32_t& lo) {
    uint32_t h0 = __float_as_uint(x0) & 0xFFFF0000u;
    uint32_t h1 = __float_as_uint(x1) & 0xFFFF0000u;
    hi = __byte_perm(h0, h1, 0x7632);
    float l0 = x0 - __uint_as_float(h0);
    float l1 = x1 - __uint_as_float(h1);
    lo = __byte_perm(__float_as_uint(l0), __float_as_uint(l1), 0x7632);
}

// ===========================================================================
// 3xBF16 GEMM, fp32 operands with INLINE splits (round-12 proven structure:
// split cost hides under mma issue; no cvt preamble needed).
//   C[m,n] = sum_k A[m,k] * W[n,k] + bias[n]
// BM=BN=128, BK=32, 256 threads (8 warps 2x4), warp tile 64x32,
// 4x4 m16n8k16 frags, Ah*Bh + Ah*Bl + Al*Bh. cp.async double buffer,
// ROWF=40 fp32 row pad.
// MODE 0: QKV (A = iQ): q fp32, k bf16-hi/lo pairs, vT bf16-hi/lo transposed
// MODE 1: output projection (A = g_ctx fp32), fp32 row-major C
// ===========================================================================
#define GK      1024
#define BKC     32
#define ROWF    40
#define TILE_F  (128 * ROWF)
#define GSM_BYTES (4 * TILE_F * 4)         // A0,W0,A1,W1

template <int MODE>
__global__ __launch_bounds__(256, 2)
void tc_gemm(const float* __restrict__ A_in, const float* __restrict__ W,
             const float* __restrict__ bias, float* __restrict__ C, int N)
{
    extern __shared__ __align__(16) float smem[];
    float* sA[2] = { smem,              smem + 2 * TILE_F };
    float* sW[2] = { smem + TILE_F,     smem + 3 * TILE_F };

    const int tid  = threadIdx.x;
    const int wid  = tid >> 5;
    const int lane = tid & 31;
    const int g    = lane >> 2;
    const int tig  = lane & 3;
    const int wm   = wid >> 2;
    const int wn   = wid & 3;
    const int mbase = wm * 64;
    const int nbase = wn * 32;

    const int bx = blockIdx.x;
    const int by = blockIdx.y;

    const float* Abase = A_in + (long)(by * 128) * GK;
    const float* Wbase = W    + (long)(bx * 128) * GK;

    const uint32_t sbase = smem_u32(smem);
    auto load_chunk = [&](int kc, int buf) {
        const uint32_t aoff = sbase + (uint32_t)((buf ? 2 * TILE_F : 0) * 4);
        const uint32_t woff = sbase + (uint32_t)(((buf ? 3 * TILE_F : TILE_F)) * 4);
#pragma unroll
        for (int i = 0; i < 4; i++) {
            int idx = tid + i * 256;          // 0..1023
            int r = idx >> 3;                 // row 0..127
            int q = idx & 7;                  // float4 in row
            uint32_t so = (uint32_t)((r * ROWF + q * 4) * 4);
            cp16(aoff + so, Abase + (long)r * GK + kc * BKC + q * 4);
            cp16(woff + so, Wbase + (long)r * GK + kc * BKC + q * 4);
        }
    };

    float acc[4][4][4];
#pragma unroll
    for (int mi = 0; mi < 4; mi++)
#pragma unroll
        for (int ni = 0; ni < 4; ni++)
#pragma unroll
            for (int r = 0; r < 4; r++) acc[mi][ni][r] = 0.f;

    load_chunk(0, 0); CP_COMMIT();
    load_chunk(1, 1); CP_COMMIT();

    const int NCH = GK / BKC;              // 32
    for (int k0 = 0; k0 < NCH; k0++) {
        const int buf = k0 & 1;
        if (k0 + 1 < NCH) { CP_WAIT(1); } else { CP_WAIT(0); }
        __syncthreads();

        const float* As = sA[buf];
        const float* Ws = sW[buf];
#pragma unroll
        for (int kk = 0; kk < 2; kk++) {
            const int k16 = kk * 16;
            uint32_t bh[4][2], bl[4][2];
#pragma unroll
            for (int ni = 0; ni < 4; ni++) {
                const int r0 = nbase + ni * 8 + g;
                float2 w0 = *(const float2*)&Ws[r0 * ROWF + k16 + 2 * tig];
                float2 w1 = *(const float2*)&Ws[r0 * ROWF + k16 + 2 * tig + 8];
                bsplit(w0.x, w0.y, bh[ni][0], bl[ni][0]);
                bsplit(w1.x, w1.y, bh[ni][1], bl[ni][1]);
            }
#pragma unroll
            for (int mi = 0; mi < 4; mi++) {
                const int r0 = mbase + mi * 16 + g;
                uint32_t ah[4], al[4];
                float2 a0 = *(const float2*)&As[r0 * ROWF + k16 + 2 * tig];
                float2 a1 = *(const float2*)&As[(r0 + 8) * ROWF + k16 + 2 * tig];
                float2 a2 = *(const float2*)&As[r0 * ROWF + k16 + 2 * tig + 8];
                float2 a3 = *(const float2*)&As[(r0 + 8) * ROWF + k16 + 2 * tig + 8];
                bsplit(a0.x, a0.y, ah[0], al[0]);
                bsplit(a1.x, a1.y, ah[1], al[1]);
                bsplit(a2.x, a2.y, ah[2], al[2]);
                bsplit(a3.x, a3.y, ah[3], al[3]);
                // pass-major (neutral-safe): reuse distance 4
#pragma unroll
                for (int ni = 0; ni < 4; ni++) mma_bf16(acc[mi][ni], ah, bh[ni]);
#pragma unroll
                for (int ni = 0; ni < 4; ni++) mma_bf16(acc[mi][ni], ah, bl[ni]);
#pragma unroll
                for (int ni = 0; ni < 4; ni++) mma_bf16(acc[mi][ni], al, bh[ni]);
            }
        }
        __syncthreads();
        if (k0 + 2 < NCH) { load_chunk(k0 + 2, buf); CP_COMMIT(); }
    }

    // Epilogue: c-frag (m16n8) rows g,g+8; cols 2tig,2tig+1 (adjacent pair)
#pragma unroll
    for (int ni = 0; ni < 4; ni++) {
        const int gcol = bx * 128 + nbase + ni * 8 + 2 * tig;
        const float b0 = bias[gcol];
        const float b1 = bias[gcol + 1];
        const int which = gcol >> 10;
        const int hh = (gcol >> 6) & 15;
        const int dd = gcol & 63;
#pragma unroll
        for (int mi = 0; mi < 4; mi++) {
#pragma unroll
            for (int h = 0; h < 2; h++) {
                const int rr = by * 128 + mbase + mi * 16 + g + h * 8;
                float2 o;
                o.x = acc[mi][ni][2 * h + 0] + b0;
                o.y = acc[mi][ni][2 * h + 1] + b1;
                if (MODE == 0) {
                    const int bb = rr >> 10, ss = rr & 1023;
                    const long bhq = (long)(bb * HN + hh);
                    if (which == 0) {
                        *(float2*)(g_q + (bhq * SQ + ss) * AD + dd) = o;
                    } else if (which == 1) {
                        uint32_t hi, lo;
                        bsplit(o.x, o.y, hi, lo);
                        const long idx = (bhq * SQ + ss) * 32 + (dd >> 1);
                        g_k_h[idx] = hi;
                        g_k_l[idx] = lo;
                    } else {
                        uint32_t hi, lo;
                        bsplit(o.x, o.y, hi, lo);
                        const long base = (bhq * AD + dd) * SQ + ss;
                        g_vT_h[base]      = (unsigned short)(hi & 0xFFFFu);
                        g_vT_h[base + SQ] = (unsigned short)(hi >> 16);
                        g_vT_l[base]      = (unsigned short)(lo & 0xFFFFu);
                        g_vT_l[base + SQ] = (unsigned short)(lo >> 16);
                    }
                } else {
                    *(float2*)(C + (long)rr * N + gcol) = o;
                }
            }
        }
    }
}

// ===========================================================================
// Tensor-core attention, register P-reuse (hot loop proven in rounds 14/15;
// epilogue writes fp32 ctx). Grid (8,16,4), 256 thr, q tile 128 rows,
// kv tiles 32 rows double-buffered, smem ~103 KB -> 2 CTAs/SM.
// ===========================================================================
#define O_QH   0                              // [128][36]
#define O_QL   (O_QH + 128*36)                // 4608
#define O_KV   (O_QL + 128*36)                // 2 buf x 4864
#define KVBUF  4864                           // KH[32][36] KL[32][36] VH[64][20] VL[64][20]
#define KV_KH  0
#define KV_KL  1152
#define KV_VH  2304
#define KV_VL  3584
#define O_RELS (O_KV + 2*KVBUF)               // fp32 [33][68]
#define O_RQS  (O_RELS + 33*68)               // fp32 [128][36]
#define A_TOTU (O_RQS + 128*36)
#define A_BYTES (A_TOTU * 4)                  // 103,184 B -> 2 CTAs/SM

__global__ __launch_bounds__(256, 2)
void attn_mma(const float* __restrict__ rel_emb, const float* __restrict__ snb_p)
{
    extern __shared__ __align__(16) uint32_t smu[];
    float* smf = (float*)smu;

    const int tid  = threadIdx.x;
    const int wid  = tid >> 5;
    const int lane = tid & 31;
    const int g    = lane >> 2;
    const int tig  = lane & 3;
    const int qt = blockIdx.x, h = blockIdx.y, b = blockIdx.z;
    const int bh = b * HN + h;
    const int q0 = qt * 128;
    const int mb = wid * 16;
    const float snb = __ldg(snb_p);

    const uint32_t sb = smem_u32(smu);

    // ---- preamble: stage q fp32 (transiently in KV area, stride 68) + rels
    const float* Qg = g_q + ((long)bh * SQ + q0) * AD;
#pragma unroll
    for (int i = 0; i < 8; i++) {
        int idx = tid + i * 256;
        int r = idx >> 4, c = idx & 15;
        cp16(sb + (uint32_t)((O_KV + r * 68 + c * 4) * 4), Qg + r * AD + c * 4);
    }
    for (int i = tid; i < 33 * 16; i += 256) {
        int r = i >> 4, c = i & 15;
        cp16(sb + (uint32_t)((O_RELS + r * 68 + c * 4) * 4), rel_emb + r * 64 + c * 4);
    }
    CP_COMMIT();
    CP_WAIT(0);
    __syncthreads();

    // q -> bf16 hi/lo (once per block)
    float* q32 = smf + O_KV;                 // [128][68] fp32 (transient)
    for (int i = tid; i < 128 * 32; i += 256) {
        int r = i >> 5, c = i & 31;
        float2 v = *(const float2*)&q32[r * 68 + c * 2];
        uint32_t hi, lo;
        bsplit(v.x, v.y, hi, lo);
        smu[O_QH + r * 36 + c] = hi;
        smu[O_QL + r * 36 + c] = lo;
    }
    // rq[r][p] = q_r . rel_emb[p]  (fp32)
    float* relf = smf + O_RELS;
    float* rqs  = smf + O_RQS;
    for (int i = tid; i < 128 * 33; i += 256) {
        int r = i / 33, p = i - r * 33;
        float s = 0.f;
#pragma unroll 16
        for (int d = 0; d < 64; d++) s = fmaf(q32[r * 68 + d], relf[p * 68 + d], s);
        rqs[r * 36 + p] = s;
    }
    __syncthreads();            // q32 reads done; KV area now free

    auto load_kv = [&](int kt, int buf) {
        const uint32_t kvb = sb + (uint32_t)((O_KV + buf * KVBUF) * 4);
        const uint32_t* Khg = g_k_h + ((long)bh * SQ + kt * 32) * 32;
        const uint32_t* Klg = g_k_l + ((long)bh * SQ + kt * 32) * 32;
        const unsigned short* Vhg = g_vT_h + (long)bh * AD * SQ + kt * 32;
        const unsigned short* Vlg = g_vT_l + (long)bh * AD * SQ + kt * 32;
        {   // K tiles: 32 rows x 8 quads, 256 threads -> 1 each per tile
            int r = tid >> 3, c = tid & 7;
            uint32_t so = (uint32_t)((r * 36 + c * 4) * 4);
            cp16(kvb + KV_KH * 4 + so, Khg + r * 32 + c * 4);
            cp16(kvb + KV_KL * 4 + so, Klg + r * 32 + c * 4);
        }
        {   // V tiles: 64 d-rows x 4 quads (16 u32 = 32 shorts along s)
            int d = tid >> 2, c = tid & 3;
            uint32_t so = (uint32_t)((d * 20 + c * 4) * 4);
            cp16(kvb + KV_VH * 4 + so, Vhg + (long)d * SQ + c * 8);
            cp16(kvb + KV_VL * 4 + so, Vlg + (long)d * SQ + c * 8);
        }
    };
    load_kv(0, 0); CP_COMMIT();
    load_kv(1, 1); CP_COMMIT();

    float oacc[8][4];
#pragma unroll
    for (int ni = 0; ni < 8; ni++)
#pragma unroll
        for (int r = 0; r < 4; r++) oacc[ni][r] = 0.f;
    float denp0 = 0.f, denp1 = 0.f;

    const uint32_t* QH = smu + O_QH;
    const uint32_t* QL = smu + O_QL;
    const int ig0 = q0 + mb + g;

    for (int kt = 0; kt < 32; kt++) {
        const int buf = kt & 1;
        if (kt + 1 < 32) { CP_WAIT(1); } else { CP_WAIT(0); }
        __syncthreads();
        const uint32_t* KH = smu + O_KV + buf * KVBUF + KV_KH;
        const uint32_t* KL = smu + O_KV + buf * KVBUF + KV_KL;
        const uint32_t* VH = smu + O_KV + buf * KVBUF + KV_VH;
        const uint32_t* VL = smu + O_KV + buf * KVBUF + KV_VL;

        // --- S = q k^T over 32 key rows; sacc[ni] covers cols ni*8..+7
        float sacc[4][4];
#pragma unroll
        for (int ni = 0; ni < 4; ni++)
#pragma unroll
            for (int r = 0; r < 4; r++) sacc[ni][r] = 0.f;
#pragma unroll
        for (int kk = 0; kk < 4; kk++) {
            const int kc = kk * 8;
            const int r0 = (mb + g) * 36 + kc + tig;
            const int r8 = r0 + 8 * 36;
            uint32_t ah[4], al[4];
            ah[0] = QH[r0]; ah[1] = QH[r8]; ah[2] = QH[r0 + 4]; ah[3] = QH[r8 + 4];
            al[0] = QL[r0]; al[1] = QL[r8]; al[2] = QL[r0 + 4]; al[3] = QL[r8 + 4];
            uint32_t kbh[4][2], kbl[4][2];
#pragma unroll
            for (int ni = 0; ni < 4; ni++) {
                const int b0 = (ni * 8 + g) * 36 + kc + tig;
                kbh[ni][0] = KH[b0]; kbh[ni][1] = KH[b0 + 4];
                kbl[ni][0] = KL[b0]; kbl[ni][1] = KL[b0 + 4];
            }
#pragma unroll
            for (int ni = 0; ni < 4; ni++) mma_bf16(sacc[ni], ah, kbh[ni]);
#pragma unroll
            for (int ni = 0; ni < 4; ni++) mma_bf16(sacc[ni], ah, kbl[ni]);
#pragma unroll
            for (int ni = 0; ni < 4; ni++) mma_bf16(sacc[ni], al, kbh[ni]);
        }

        // --- elementwise in registers: t = relu((S+rel)/8 + b)^2, split ---
        uint32_t tha[4], tla[4], thb[4], tlb[4];
#pragma unroll
        for (int ni = 0; ni < 4; ni++) {
            const int cbase = ni * 8 + 2 * tig;
            const int jbase = kt * 32 + cbase;
            {   // row g
                int d0 = jbase - ig0;     d0 = (d0 < -KREL) ? -KREL : ((d0 > KREL) ? KREL : d0);
                int d1 = jbase + 1 - ig0; d1 = (d1 < -KREL) ? -KREL : ((d1 > KREL) ? KREL : d1);
                float s0 = (sacc[ni][0] + rqs[(mb + g) * 36 + d0 + KREL]) * 0.125f + snb;
                float s1 = (sacc[ni][1] + rqs[(mb + g) * 36 + d1 + KREL]) * 0.125f + snb;
                s0 = fmaxf(s0, 0.f); s1 = fmaxf(s1, 0.f);
                float t0 = s0 * s0, t1 = s1 * s1;
                denp0 += t0 + t1;
                bsplit(t0, t1, tha[ni], tla[ni]);
            }
            {   // row g+8
                int d0 = jbase - (ig0 + 8);     d0 = (d0 < -KREL) ? -KREL : ((d0 > KREL) ? KREL : d0);
                int d1 = jbase + 1 - (ig0 + 8); d1 = (d1 < -KREL) ? -KREL : ((d1 > KREL) ? KREL : d1);
                float s0 = (sacc[ni][2] + rqs[(mb + g + 8) * 36 + d0 + KREL]) * 0.125f + snb;
                float s1 = (sacc[ni][3] + rqs[(mb + g + 8) * 36 + d1 + KREL]) * 0.125f + snb;
                s0 = fmaxf(s0, 0.f); s1 = fmaxf(s1, 0.f);
                float t0 = s0 * s0, t1 = s1 * s1;
                denp1 += t0 + t1;
                bsplit(t0, t1, thb[ni], tlb[ni]);
            }
        }

        // --- O += t V ; A-frag is the in-register t; pass-major ---
#pragma unroll
        for (int kk2 = 0; kk2 < 2; kk2++) {
            uint32_t ah[4], al[4];
            ah[0] = tha[2 * kk2];     al[0] = tla[2 * kk2];
            ah[1] = thb[2 * kk2];     al[1] = tlb[2 * kk2];
            ah[2] = tha[2 * kk2 + 1]; al[2] = tla[2 * kk2 + 1];
            ah[3] = thb[2 * kk2 + 1]; al[3] = tlb[2 * kk2 + 1];
#pragma unroll
            for (int ni = 0; ni < 8; ni++) {     // pass hh
                const int b0 = (ni * 8 + g) * 20 + kk2 * 8 + tig;
                uint32_t bh2[2] = { VH[b0], VH[b0 + 4] };
                mma_bf16(oacc[ni], ah, bh2);
            }
#pragma unroll
            for (int ni = 0; ni < 8; ni++) {     // pass hl
                const int b0 = (ni * 8 + g) * 20 + kk2 * 8 + tig;
                uint32_t bl2[2] = { VL[b0], VL[b0 + 4] };
                mma_bf16(oacc[ni], ah, bl2);
            }
#pragma unroll
            for (int ni = 0; ni < 8; ni++) {     // pass lh
                const int b0 = (ni * 8 + g) * 20 + kk2 * 8 + tig;
                uint32_t bh2[2] = { VH[b0], VH[b0 + 4] };
                mma_bf16(oacc[ni], al, bh2);
            }
        }
        __syncthreads();        // all warps done with kv[buf] before refill
        if (kt + 2 < 32) { load_kv(kt + 2, buf); CP_COMMIT(); }
    }

    // deterministic den reduction across the 4 tig lanes
    denp0 += __shfl_xor_sync(0xffffffffu, denp0, 1);
    denp0 += __shfl_xor_sync(0xffffffffu, denp0, 2);
    denp1 += __shfl_xor_sync(0xffffffffu, denp1, 1);
    denp1 += __shfl_xor_sync(0xffffffffu, denp1, 2);
    const float inv0 = 1.f / (denp0 + SN_EPS);
    const float inv1 = 1.f / (denp1 + SN_EPS);

    // ctx written fp32 (gemm1 splits inline)
    float* ctx0 = g_ctx + (long)(b * SQ + q0 + mb + g) * DM + h * AD;
    float* ctx8 = ctx0 + 8 * DM;
#pragma unroll
    for (int ni = 0; ni < 8; ni++) {
        const int c = ni * 8 + 2 * tig;
        *(float2*)(ctx0 + c) = make_float2(oacc[ni][0] * inv0, oacc[ni][1] * inv0);
        *(float2*)(ctx8 + c) = make_float2(oacc[ni][2] * inv1, oacc[ni][3] * inv1);
    }
}

// ===========================================================================
extern "C" void kernel_launch(void* const* d_in, const int* in_sizes, int n_in,
                              void* d_out, int out_size)
{
    (void)in_sizes; (void)n_in; (void)out_size;
    const float* iQ  = (const float*)d_in[0];
    const float* Wa  = (const float*)d_in[1];
    const float* ba  = (const float*)d_in[2];
    const float* rel = (const float*)d_in[3];
    const float* snb = (const float*)d_in[4];
    const float* Wo  = (const float*)d_in[5];
    const float* bo  = (const float*)d_in[6];
    float* out = (float*)d_out;

    cudaFuncSetAttribute(tc_gemm<0>, cudaFuncAttributeMaxDynamicSharedMemorySize, GSM_BYTES);
    cudaFuncSetAttribute(tc_gemm<1>, cudaFuncAttributeMaxDynamicSharedMemorySize, GSM_BYTES);
    cudaFuncSetAttribute(attn_mma,   cudaFuncAttributeMaxDynamicSharedMemorySize, A_BYTES);

    float* ctx;
    cudaGetSymbolAddress((void**)&ctx, g_ctx);

    // 1) QKV projection (fp32 inputs, inline 3xBF16 splits)
    tc_gemm<0><<<dim3(3072 / 128, 4096 / 128), 256, GSM_BYTES>>>(iQ, Wa, ba, nullptr, 3072);

    // 2) tensor-core attention + SparseNormer -> g_ctx (fp32)
    attn_mma<<<dim3(SQ / 128, HN, NB), 256, A_BYTES>>>(rel, snb);

    // 3) output projection (fp32 inputs, inline splits)
    tc_gemm<1><<<dim3(1024 / 128, 4096 / 128), 256, GSM_BYTES>>>(ctx, Wo, bo, out, 1024);
}